// round 2
// baseline (speedup 1.0000x reference)
#include <cuda_runtime.h>

#define SEQ   2048
#define DIM   4096
#define BATCH 4
#define PAD_ID 50256

// ---------------------------------------------------------------------------
// Kernel 1: rewards[b*SEQ+s] = dot(hidden_states[b,s,:], w)   (8*2048 rows)
// One warp per row, float4 loads, warp shuffle reduction. Pure HBM stream.
// ---------------------------------------------------------------------------
__global__ void reward_matvec_kernel(const float* __restrict__ hs,
                                     const float* __restrict__ w,
                                     float* __restrict__ rewards,
                                     int n_rows) {
    int gwarp = (blockIdx.x * blockDim.x + threadIdx.x) >> 5;
    int lane  = threadIdx.x & 31;
    if (gwarp >= n_rows) return;

    const float4* row = reinterpret_cast<const float4*>(hs + (size_t)gwarp * DIM);
    const float4* w4  = reinterpret_cast<const float4*>(w);

    float acc = 0.0f;
    // DIM/4 = 1024 float4 per row; 32 per lane. Unroll for MLP.
    #pragma unroll 8
    for (int i = lane; i < DIM / 4; i += 32) {
        float4 a = __ldg(&row[i]);
        float4 b = __ldg(&w4[i]);
        acc = fmaf(a.x, b.x, acc);
        acc = fmaf(a.y, b.y, acc);
        acc = fmaf(a.z, b.z, acc);
        acc = fmaf(a.w, b.w, acc);
    }
    #pragma unroll
    for (int off = 16; off > 0; off >>= 1)
        acc += __shfl_xor_sync(0xffffffffu, acc, off);
    if (lane == 0) rewards[gwarp] = acc;
}

// ---------------------------------------------------------------------------
// Kernel 2: per-pair stats + loss. Single block, 1024 threads (32 warps).
// ids are INT32 (JAX x64-disabled: astype(int64) silently yields int32).
// ---------------------------------------------------------------------------
__global__ void __launch_bounds__(1024, 1)
reward_stats_kernel(const int* __restrict__ ids,
                    const float* __restrict__ rewards,  // [2*BATCH, SEQ]
                    float* __restrict__ out) {          // layout per header
    __shared__ int   sh_min[3];          // div, c_pad, r_pad
    __shared__ float sh_c[32], sh_r[32], sh_l[32];
    __shared__ int   sh_n[32];
    __shared__ float sh_loss;

    const int tid    = threadIdx.x;
    const int lane   = tid & 31;
    const int warp   = tid >> 5;
    const int nwarps = blockDim.x >> 5;   // 32

    if (tid == 0) sh_loss = 0.0f;

    float* out_cm = out + 1 + 2 * BATCH * SEQ;      // chosen_mean[4]
    float* out_rm = out_cm + BATCH;                 // rejected_mean[4]
    float* out_ce = out_rm + BATCH;                 // chosen_end[4]
    float* out_re = out_ce + BATCH;                 // rejected_end[4]

    for (int b = 0; b < BATCH; b++) {
        __syncthreads();
        if (tid < 3) sh_min[tid] = SEQ;
        __syncthreads();

        // --- pass 1: first-index searches ---
        int dloc = SEQ, cloc = SEQ, rloc = SEQ;
        for (int s = tid; s < SEQ; s += blockDim.x) {
            int c = ids[(size_t)b * SEQ + s];
            int r = ids[(size_t)(b + BATCH) * SEQ + s];
            if (c != r)      dloc = min(dloc, s);
            if (c == PAD_ID) cloc = min(cloc, s);
            if (r == PAD_ID) rloc = min(rloc, s);
        }
        atomicMin(&sh_min[0], dloc);
        atomicMin(&sh_min[1], cloc);
        atomicMin(&sh_min[2], rloc);
        __syncthreads();

        const int div_i = sh_min[0];
        const int end_i = max(sh_min[1], sh_min[2]);

        // --- pass 2: masked sums ---
        float sc = 0.0f, sr = 0.0f, sl = 0.0f;
        int   cnt = 0;
        for (int s = tid; s < SEQ; s += blockDim.x) {
            if (s >= div_i && s < end_i) {
                float cr = rewards[(size_t)b * SEQ + s];
                float rr = rewards[(size_t)(b + BATCH) * SEQ + s];
                sc += cr;
                sr += rr;
                float x = cr - rr;
                // -log_sigmoid(x) = max(-x,0) + log1p(exp(-|x|))
                sl += fmaxf(-x, 0.0f) + log1pf(expf(-fabsf(x)));
                cnt++;
            }
        }
        // warp reduce
        #pragma unroll
        for (int off = 16; off > 0; off >>= 1) {
            sc  += __shfl_xor_sync(0xffffffffu, sc,  off);
            sr  += __shfl_xor_sync(0xffffffffu, sr,  off);
            sl  += __shfl_xor_sync(0xffffffffu, sl,  off);
            cnt += __shfl_xor_sync(0xffffffffu, cnt, off);
        }
        if (lane == 0) { sh_c[warp] = sc; sh_r[warp] = sr; sh_l[warp] = sl; sh_n[warp] = cnt; }
        __syncthreads();

        if (warp == 0) {
            float c0 = (lane < nwarps) ? sh_c[lane] : 0.0f;
            float r0 = (lane < nwarps) ? sh_r[lane] : 0.0f;
            float l0 = (lane < nwarps) ? sh_l[lane] : 0.0f;
            int   n0 = (lane < nwarps) ? sh_n[lane] : 0;
            #pragma unroll
            for (int off = 16; off > 0; off >>= 1) {
                c0 += __shfl_xor_sync(0xffffffffu, c0, off);
                r0 += __shfl_xor_sync(0xffffffffu, r0, off);
                l0 += __shfl_xor_sync(0xffffffffu, l0, off);
                n0 += __shfl_xor_sync(0xffffffffu, n0, off);
            }
            if (lane == 0) {
                float fcnt = fmaxf((float)n0, 1.0f);
                out_cm[b] = c0 / fcnt;
                out_rm[b] = r0 / fcnt;
                int last = max(end_i - 1, 0);
                out_ce[b] = rewards[(size_t)b * SEQ + last];
                out_re[b] = rewards[(size_t)(b + BATCH) * SEQ + last];
                sh_loss += l0 / fcnt;
            }
        }
        __syncthreads();
    }
    if (tid == 0) out[0] = sh_loss / (float)BATCH;
}

// ---------------------------------------------------------------------------
extern "C" void kernel_launch(void* const* d_in, const int* in_sizes, int n_in,
                              void* d_out, int out_size) {
    const float* hs  = (const float*)d_in[0];       // (2B, S, D) fp32
    const float* w   = (const float*)d_in[1];       // (D,) fp32
    const int*   ids = (const int*)d_in[2];         // (2B, S) int32

    float* out = (float*)d_out;
    float* rewards = out + 1;            // rewards occupy out[1 .. 1+16384)

    const int n_rows = 2 * BATCH * SEQ;  // 16384
    const int threads = 256;             // 8 warps/block
    const int blocks = (n_rows * 32 + threads - 1) / threads;  // 2048

    reward_matvec_kernel<<<blocks, threads>>>(hs, w, rewards, n_rows);
    reward_stats_kernel<<<1, 1024>>>(ids, rewards, out);
}

// round 3
// speedup vs baseline: 1.1953x; 1.1953x over previous
#include <cuda_runtime.h>

#define SEQ   2048
#define DIM   4096
#define BATCH 4
#define PAD_ID 50256

// ---------------------------------------------------------------------------
// Kernel 1: rewards[b*SEQ+s] = dot(hidden_states[b,s,:], w)   (8*2048 rows)
// One warp per row, float4 loads, warp shuffle reduction. Pure HBM stream.
// Also zeroes out[0] (loss accumulator) since d_out is poisoned.
// ---------------------------------------------------------------------------
__global__ void reward_matvec_kernel(const float* __restrict__ hs,
                                     const float* __restrict__ w,
                                     float* __restrict__ rewards,
                                     float* __restrict__ loss_slot,
                                     int n_rows) {
    int gwarp = (blockIdx.x * blockDim.x + threadIdx.x) >> 5;
    int lane  = threadIdx.x & 31;
    if (gwarp >= n_rows) return;
    if (gwarp == 0 && lane == 0) *loss_slot = 0.0f;

    const float4* row = reinterpret_cast<const float4*>(hs + (size_t)gwarp * DIM);
    const float4* w4  = reinterpret_cast<const float4*>(w);

    float acc = 0.0f;
    #pragma unroll 8
    for (int i = lane; i < DIM / 4; i += 32) {
        float4 a = __ldg(&row[i]);
        float4 b = __ldg(&w4[i]);
        acc = fmaf(a.x, b.x, acc);
        acc = fmaf(a.y, b.y, acc);
        acc = fmaf(a.z, b.z, acc);
        acc = fmaf(a.w, b.w, acc);
    }
    #pragma unroll
    for (int off = 16; off > 0; off >>= 1)
        acc += __shfl_xor_sync(0xffffffffu, acc, off);
    if (lane == 0) rewards[gwarp] = acc;
}

// ---------------------------------------------------------------------------
// Kernel 2: per-pair stats + loss. One block per batch pair (grid = BATCH).
// ids are INT32 (JAX x64-disabled). Loss accumulated via atomicAdd into out[0].
// ---------------------------------------------------------------------------
__global__ void __launch_bounds__(1024, 1)
reward_stats_kernel(const int* __restrict__ ids,
                    const float* __restrict__ rewards,  // [2*BATCH, SEQ]
                    float* __restrict__ out) {
    __shared__ int   sh_min[3];          // div, c_pad, r_pad
    __shared__ float sh_c[32], sh_r[32], sh_l[32];
    __shared__ int   sh_n[32];

    const int b      = blockIdx.x;
    const int tid    = threadIdx.x;
    const int lane   = tid & 31;
    const int warp   = tid >> 5;
    const int nwarps = blockDim.x >> 5;   // 32

    float* out_cm = out + 1 + 2 * BATCH * SEQ;      // chosen_mean[4]
    float* out_rm = out_cm + BATCH;                 // rejected_mean[4]
    float* out_ce = out_rm + BATCH;                 // chosen_end[4]
    float* out_re = out_ce + BATCH;                 // rejected_end[4]

    if (tid < 3) sh_min[tid] = SEQ;
    __syncthreads();

    // --- pass 1: first-index searches (2 tokens per thread) ---
    int dloc = SEQ, cloc = SEQ, rloc = SEQ;
    #pragma unroll
    for (int s = tid; s < SEQ; s += 1024) {
        int c = __ldg(&ids[(size_t)b * SEQ + s]);
        int r = __ldg(&ids[(size_t)(b + BATCH) * SEQ + s]);
        if (c != r)      dloc = min(dloc, s);
        if (c == PAD_ID) cloc = min(cloc, s);
        if (r == PAD_ID) rloc = min(rloc, s);
    }
    atomicMin(&sh_min[0], dloc);
    atomicMin(&sh_min[1], cloc);
    atomicMin(&sh_min[2], rloc);
    __syncthreads();

    const int div_i = sh_min[0];
    const int end_i = max(sh_min[1], sh_min[2]);

    // --- pass 2: masked sums ---
    float sc = 0.0f, sr = 0.0f, sl = 0.0f;
    int   cnt = 0;
    #pragma unroll
    for (int s = tid; s < SEQ; s += 1024) {
        if (s >= div_i && s < end_i) {
            float cr = __ldg(&rewards[(size_t)b * SEQ + s]);
            float rr = __ldg(&rewards[(size_t)(b + BATCH) * SEQ + s]);
            sc += cr;
            sr += rr;
            float x = cr - rr;
            // -log_sigmoid(x) = max(-x,0) + log1p(exp(-|x|))
            sl += fmaxf(-x, 0.0f) + log1pf(expf(-fabsf(x)));
            cnt++;
        }
    }
    #pragma unroll
    for (int off = 16; off > 0; off >>= 1) {
        sc  += __shfl_xor_sync(0xffffffffu, sc,  off);
        sr  += __shfl_xor_sync(0xffffffffu, sr,  off);
        sl  += __shfl_xor_sync(0xffffffffu, sl,  off);
        cnt += __shfl_xor_sync(0xffffffffu, cnt, off);
    }
    if (lane == 0) { sh_c[warp] = sc; sh_r[warp] = sr; sh_l[warp] = sl; sh_n[warp] = cnt; }
    __syncthreads();

    if (warp == 0) {
        float c0 = (lane < nwarps) ? sh_c[lane] : 0.0f;
        float r0 = (lane < nwarps) ? sh_r[lane] : 0.0f;
        float l0 = (lane < nwarps) ? sh_l[lane] : 0.0f;
        int   n0 = (lane < nwarps) ? sh_n[lane] : 0;
        #pragma unroll
        for (int off = 16; off > 0; off >>= 1) {
            c0 += __shfl_xor_sync(0xffffffffu, c0, off);
            r0 += __shfl_xor_sync(0xffffffffu, r0, off);
            l0 += __shfl_xor_sync(0xffffffffu, l0, off);
            n0 += __shfl_xor_sync(0xffffffffu, n0, off);
        }
        if (lane == 0) {
            float fcnt = fmaxf((float)n0, 1.0f);
            out_cm[b] = c0 / fcnt;
            out_rm[b] = r0 / fcnt;
            int last = max(end_i - 1, 0);
            out_ce[b] = __ldg(&rewards[(size_t)b * SEQ + last]);
            out_re[b] = __ldg(&rewards[(size_t)(b + BATCH) * SEQ + last]);
            atomicAdd(out, l0 / fcnt * (1.0f / (float)BATCH));
        }
    }
}

// ---------------------------------------------------------------------------
extern "C" void kernel_launch(void* const* d_in, const int* in_sizes, int n_in,
                              void* d_out, int out_size) {
    const float* hs  = (const float*)d_in[0];       // (2B, S, D) fp32
    const float* w   = (const float*)d_in[1];       // (D,) fp32
    const int*   ids = (const int*)d_in[2];         // (2B, S) int32

    float* out = (float*)d_out;
    float* rewards = out + 1;            // rewards occupy out[1 .. 1+16384)

    const int n_rows = 2 * BATCH * SEQ;  // 16384
    const int threads = 256;             // 8 warps/block
    const int blocks = (n_rows * 32 + threads - 1) / threads;  // 2048

    reward_matvec_kernel<<<blocks, threads>>>(hs, w, rewards, out, n_rows);
    reward_stats_kernel<<<BATCH, 1024>>>(ids, rewards, out);
}

// round 5
// speedup vs baseline: 1.2053x; 1.0083x over previous
#include <cuda_runtime.h>

#define SEQ    2048
#define DIM    4096
#define BATCH  4
#define PAD_ID 50256
#define NROWS  (2 * BATCH * SEQ)     // 16384
#define TPB    256                   // 8 warps/block, 8 rows/block
#define NBLK   (NROWS / 8)           // 2048 blocks

__device__ unsigned int g_counter = 0;

// ---------------------------------------------------------------------------
// Fused kernel: matvec rewards + (last 4 blocks) per-pair stats & loss.
// ---------------------------------------------------------------------------
__global__ void __launch_bounds__(TPB, 1)
reward_fused_kernel(const float* __restrict__ hs,
                    const float* __restrict__ w,
                    const int*   __restrict__ ids,
                    float*       __restrict__ out) {
    float* rewards = out + 1;                       // [2B*S] (4-byte aligned only!)
    const int tid  = threadIdx.x;
    const int lane = tid & 31;
    const int warp = tid >> 5;

    // ---- matvec: one warp per row ----
    int gwarp = blockIdx.x * (TPB / 32) + warp;
    if (gwarp == 0 && lane == 0) out[0] = 0.0f;     // zero loss slot (d_out poisoned)

    {
        const float4* row = reinterpret_cast<const float4*>(hs + (size_t)gwarp * DIM);
        const float4* w4  = reinterpret_cast<const float4*>(w);
        float acc = 0.0f;
        #pragma unroll 8
        for (int i = lane; i < DIM / 4; i += 32) {
            float4 a = __ldg(&row[i]);
            float4 b = __ldg(&w4[i]);
            acc = fmaf(a.x, b.x, acc);
            acc = fmaf(a.y, b.y, acc);
            acc = fmaf(a.z, b.z, acc);
            acc = fmaf(a.w, b.w, acc);
        }
        #pragma unroll
        for (int off = 16; off > 0; off >>= 1)
            acc += __shfl_xor_sync(0xffffffffu, acc, off);
        if (lane == 0) rewards[gwarp] = acc;
    }

    // ---- arrival ticket ----
    __shared__ unsigned int sh_ticket;
    __syncthreads();
    if (tid == 0) {
        __threadfence();                            // publish rewards (+ out[0])
        unsigned int t = atomicAdd(&g_counter, 1u);
        if (t == (unsigned)gridDim.x - 1u)
            atomicExch(&g_counter, 0u);             // reset for next graph replay
        sh_ticket = t;
    }
    __syncthreads();
    const unsigned int ticket = sh_ticket;
    if (ticket < (unsigned)gridDim.x - BATCH) return;

    // ---- stats tail: this block owns pair b ----
    const int b = gridDim.x - 1 - (int)ticket;      // 0..BATCH-1
    __threadfence();                                // acquire side

    __shared__ int   sh_min[3];
    __shared__ float sh_c[8], sh_r[8], sh_l[8];
    __shared__ int   sh_n[8];
    if (tid < 3) sh_min[tid] = SEQ;
    __syncthreads();

    // pass 1: first-index searches (int4 loads — ids base is 16B-aligned)
    {
        const int4* cid4 = reinterpret_cast<const int4*>(ids + (size_t)b * SEQ);
        const int4* rid4 = reinterpret_cast<const int4*>(ids + (size_t)(b + BATCH) * SEQ);
        int dloc = SEQ, cloc = SEQ, rloc = SEQ;
        #pragma unroll
        for (int i = tid; i < SEQ / 4; i += TPB) {
            int4 c = cid4[i];
            int4 r = rid4[i];
            int s = i * 4;
            if (c.x != r.x)      dloc = min(dloc, s + 0);
            if (c.y != r.y)      dloc = min(dloc, s + 1);
            if (c.z != r.z)      dloc = min(dloc, s + 2);
            if (c.w != r.w)      dloc = min(dloc, s + 3);
            if (c.x == PAD_ID)   cloc = min(cloc, s + 0);
            if (c.y == PAD_ID)   cloc = min(cloc, s + 1);
            if (c.z == PAD_ID)   cloc = min(cloc, s + 2);
            if (c.w == PAD_ID)   cloc = min(cloc, s + 3);
            if (r.x == PAD_ID)   rloc = min(rloc, s + 0);
            if (r.y == PAD_ID)   rloc = min(rloc, s + 1);
            if (r.z == PAD_ID)   rloc = min(rloc, s + 2);
            if (r.w == PAD_ID)   rloc = min(rloc, s + 3);
        }
        atomicMin(&sh_min[0], dloc);
        atomicMin(&sh_min[1], cloc);
        atomicMin(&sh_min[2], rloc);
    }
    __syncthreads();

    const int div_i = sh_min[0];
    const int end_i = max(sh_min[1], sh_min[2]);

    // pass 2: masked sums — SCALAR loads (rewards base is out+1, not 16B-aligned)
    float sc = 0.0f, sr = 0.0f, sl = 0.0f;
    int   cnt = 0;
    {
        const float* crp = rewards + (size_t)b * SEQ;
        const float* rrp = rewards + (size_t)(b + BATCH) * SEQ;
        #pragma unroll 4
        for (int s = tid; s < SEQ; s += TPB) {
            if (s >= div_i && s < end_i) {
                float cv = __ldg(&crp[s]);
                float rv = __ldg(&rrp[s]);
                sc += cv;
                sr += rv;
                float x = cv - rv;
                sl += fmaxf(-x, 0.0f) + log1pf(expf(-fabsf(x)));
                cnt++;
            }
        }
    }
    #pragma unroll
    for (int off = 16; off > 0; off >>= 1) {
        sc  += __shfl_xor_sync(0xffffffffu, sc,  off);
        sr  += __shfl_xor_sync(0xffffffffu, sr,  off);
        sl  += __shfl_xor_sync(0xffffffffu, sl,  off);
        cnt += __shfl_xor_sync(0xffffffffu, cnt, off);
    }
    if (lane == 0) { sh_c[warp] = sc; sh_r[warp] = sr; sh_l[warp] = sl; sh_n[warp] = cnt; }
    __syncthreads();

    if (warp == 0) {
        float c0 = (lane < 8) ? sh_c[lane] : 0.0f;
        float r0 = (lane < 8) ? sh_r[lane] : 0.0f;
        float l0 = (lane < 8) ? sh_l[lane] : 0.0f;
        int   n0 = (lane < 8) ? sh_n[lane] : 0;
        #pragma unroll
        for (int off = 4; off > 0; off >>= 1) {
            c0 += __shfl_xor_sync(0xffu, c0, off);
            r0 += __shfl_xor_sync(0xffu, r0, off);
            l0 += __shfl_xor_sync(0xffu, l0, off);
            n0 += __shfl_xor_sync(0xffu, n0, off);
        }
        if (lane == 0) {
            float* out_cm = out + 1 + NROWS;        // chosen_mean[4]
            float* out_rm = out_cm + BATCH;         // rejected_mean[4]
            float* out_ce = out_rm + BATCH;         // chosen_end[4]
            float* out_re = out_ce + BATCH;         // rejected_end[4]
            float fcnt = fmaxf((float)n0, 1.0f);
            out_cm[b] = c0 / fcnt;
            out_rm[b] = r0 / fcnt;
            int last = max(end_i - 1, 0);
            out_ce[b] = rewards[(size_t)b * SEQ + last];
            out_re[b] = rewards[(size_t)(b + BATCH) * SEQ + last];
            atomicAdd(out, l0 / fcnt * (1.0f / (float)BATCH));
        }
    }
}

// ---------------------------------------------------------------------------
extern "C" void kernel_launch(void* const* d_in, const int* in_sizes, int n_in,
                              void* d_out, int out_size) {
    const float* hs  = (const float*)d_in[0];       // (2B, S, D) fp32
    const float* w   = (const float*)d_in[1];       // (D,) fp32
    const int*   ids = (const int*)d_in[2];         // (2B, S) int32

    reward_fused_kernel<<<NBLK, TPB>>>(hs, w, ids, (float*)d_out);
}